// round 1
// baseline (speedup 1.0000x reference)
#include <cuda_runtime.h>
#include <cuda_bf16.h>
#include <math.h>
#include <stdint.h>

#define VOCAB 50000
#define DIM   300
#define BATCH 1024
#define CTX   10
#define KPAD  304   // 19 * 16, zero-padded K for mma k16 steps

// Scratch (no allocs allowed): pooled embeddings in bf16, per-row logsumexp.
__device__ __nv_bfloat16 g_pooled[BATCH * KPAD];
__device__ float g_lse[BATCH];

// ---------------------------------------------------------------------------
// Kernel 1: masked-mean pooling.  pooled[b,d] = (1/CTX) * sum_c [id!=pad] W_proj[d, id]
// W_proj is [DIM, VOCAB] row-major -> element (d, id) at d*VOCAB + id.
// ---------------------------------------------------------------------------
__global__ void pool_kernel(const int* __restrict__ ctx,
                            const float* __restrict__ Wp,
                            const int* __restrict__ pad_idx) {
    int b = blockIdx.x;
    __shared__ int ids[CTX];
    __shared__ int pad;
    if (threadIdx.x < CTX) ids[threadIdx.x] = ctx[b * CTX + threadIdx.x];
    if (threadIdx.x == 0)  pad = *pad_idx;
    __syncthreads();

    int d = threadIdx.x;
    if (d < KPAD) {
        float s = 0.f;
        if (d < DIM) {
            #pragma unroll
            for (int c = 0; c < CTX; ++c) {
                int id = ids[c];
                if (id != pad) s += Wp[(long)d * VOCAB + id];
            }
            s *= (1.0f / CTX);
        }
        g_pooled[b * KPAD + d] = __float2bfloat16(s);   // d in [300,304) -> 0 pad
    }
}

// ---------------------------------------------------------------------------
// Kernel 2: logits[b,v] = sum_d pooled[b,d] * W_cls[v,d] + b_cls[v]
// bf16 mma.sync m16n8k16, fp32 accumulate.
// Block tile: M(vocab)=128, N(batch)=128, K-step 16, 19 steps (K padded 304).
// 8 warps = 2(m) x 4(n), warp tile 64x32 = 4x4 mma fragments.
// grid = (8 n-tiles fastest, 391 m-tiles) so the 8 blocks sharing a W_cls tile
// run adjacently -> W_cls read ~once from DRAM, 7x from L2.
// ---------------------------------------------------------------------------
__global__ void __launch_bounds__(256, 2)
gemm_kernel(const float* __restrict__ Wc,
            const float* __restrict__ bc,
            float* __restrict__ out) {
    const int bbase = blockIdx.x * 128;   // batch tile base
    const int vbase = blockIdx.y * 128;   // vocab tile base

    __shared__ uint32_t As[128][8];   // W_cls tile: [m-row][k-pair] (2 bf16 per u32)
    __shared__ uint32_t Bs[128][8];   // pooled tile: [n-row][k-pair]

    const int tid  = threadIdx.x;
    const int lane = tid & 31;
    const int w    = tid >> 5;
    const int g    = lane >> 2;   // 0..7
    const int t    = lane & 3;    // 0..3
    const int wm   = w >> 2;      // 0..1
    const int wn   = w & 3;       // 0..3

    float acc[4][4][4];
    #pragma unroll
    for (int mi = 0; mi < 4; ++mi)
        #pragma unroll
        for (int ni = 0; ni < 4; ++ni)
            #pragma unroll
            for (int r = 0; r < 4; ++r) acc[mi][ni][r] = 0.f;

    const uint32_t* pooled_u32 = (const uint32_t*)g_pooled;  // KPAD/2 = 152 u32 per row

    for (int ks = 0; ks < 19; ++ks) {
        const int kk = ks * 16;

        // Load + convert A (W_cls fp32 -> bf16 pairs). 128 rows * 4 float4 each.
        #pragma unroll
        for (int it = 0; it < 2; ++it) {
            int idx  = tid + it * 256;          // 0..511
            int row  = idx >> 2;
            int quad = idx & 3;
            int v    = vbase + row;
            int col  = kk + quad * 4;
            float4 f = make_float4(0.f, 0.f, 0.f, 0.f);
            if (v < VOCAB && col < DIM)         // tail step (kk=288): quad 3 -> zero
                f = *(const float4*)(Wc + (long)v * DIM + col);
            __nv_bfloat162 p0 = __float22bfloat162_rn(make_float2(f.x, f.y));
            __nv_bfloat162 p1 = __float22bfloat162_rn(make_float2(f.z, f.w));
            As[row][quad * 2]     = *(uint32_t*)&p0;
            As[row][quad * 2 + 1] = *(uint32_t*)&p1;
        }
        // Load B (pooled already bf16, zero-padded to 304).
        #pragma unroll
        for (int it = 0; it < 4; ++it) {
            int idx = tid + it * 256;           // 0..1023
            int n   = idx >> 3;
            int wj  = idx & 7;
            Bs[n][wj] = pooled_u32[(bbase + n) * (KPAD / 2) + ks * 8 + wj];
        }
        __syncthreads();

        uint32_t a[4][4], bf[4][2];
        #pragma unroll
        for (int mi = 0; mi < 4; ++mi) {
            int r = wm * 64 + mi * 16;
            a[mi][0] = As[r + g][t];
            a[mi][1] = As[r + g + 8][t];
            a[mi][2] = As[r + g][t + 4];
            a[mi][3] = As[r + g + 8][t + 4];
        }
        #pragma unroll
        for (int ni = 0; ni < 4; ++ni) {
            int c = wn * 32 + ni * 8 + g;
            bf[ni][0] = Bs[c][t];
            bf[ni][1] = Bs[c][t + 4];
        }

        #pragma unroll
        for (int mi = 0; mi < 4; ++mi) {
            #pragma unroll
            for (int ni = 0; ni < 4; ++ni) {
                asm volatile(
                    "mma.sync.aligned.m16n8k16.row.col.f32.bf16.bf16.f32 "
                    "{%0,%1,%2,%3}, {%4,%5,%6,%7}, {%8,%9}, {%0,%1,%2,%3};\n"
                    : "+f"(acc[mi][ni][0]), "+f"(acc[mi][ni][1]),
                      "+f"(acc[mi][ni][2]), "+f"(acc[mi][ni][3])
                    : "r"(a[mi][0]), "r"(a[mi][1]), "r"(a[mi][2]), "r"(a[mi][3]),
                      "r"(bf[ni][0]), "r"(bf[ni][1]));
            }
        }
        __syncthreads();
    }

    // Epilogue: +bias, write logits.  d-frag: d0=(vg,bg) d1=(vg,bg+1) d2=(vg+8,bg) d3=(vg+8,bg+1)
    #pragma unroll
    for (int mi = 0; mi < 4; ++mi) {
        int vg0 = vbase + wm * 64 + mi * 16 + g;
        int vg1 = vg0 + 8;
        float bias0 = (vg0 < VOCAB) ? bc[vg0] : 0.f;
        float bias1 = (vg1 < VOCAB) ? bc[vg1] : 0.f;
        #pragma unroll
        for (int ni = 0; ni < 4; ++ni) {
            int bg = bbase + wn * 32 + ni * 8 + 2 * t;
            if (vg0 < VOCAB) {
                out[(long)bg * VOCAB + vg0]       = acc[mi][ni][0] + bias0;
                out[(long)(bg + 1) * VOCAB + vg0] = acc[mi][ni][1] + bias0;
            }
            if (vg1 < VOCAB) {
                out[(long)bg * VOCAB + vg1]       = acc[mi][ni][2] + bias1;
                out[(long)(bg + 1) * VOCAB + vg1] = acc[mi][ni][3] + bias1;
            }
        }
    }
}

// ---------------------------------------------------------------------------
// Kernel 3: per-row online logsumexp over VOCAB.
// ---------------------------------------------------------------------------
__global__ void lse_kernel(const float* __restrict__ out) {
    int b = blockIdx.x;
    const float* row = out + (long)b * VOCAB;

    float m = -INFINITY, s = 0.f;
    for (int v = threadIdx.x; v < VOCAB; v += blockDim.x) {
        float x  = row[v];
        float nm = fmaxf(m, x);
        s = s * __expf(m - nm) + __expf(x - nm);
        m = nm;
    }
    __shared__ float sm[256], ss[256];
    sm[threadIdx.x] = m; ss[threadIdx.x] = s;
    __syncthreads();
    for (int off = 128; off > 0; off >>= 1) {
        if (threadIdx.x < off) {
            float m2 = sm[threadIdx.x + off], s2 = ss[threadIdx.x + off];
            float m1 = sm[threadIdx.x],       s1 = ss[threadIdx.x];
            float nm = fmaxf(m1, m2);
            ss[threadIdx.x] = s1 * __expf(m1 - nm) + s2 * __expf(m2 - nm);
            sm[threadIdx.x] = nm;
        }
        __syncthreads();
    }
    if (threadIdx.x == 0) g_lse[b] = sm[0] + logf(ss[0]);
}

// ---------------------------------------------------------------------------
// Kernel 4: out[b,v] -= lse[b], float4 vectorized (VOCAB % 4 == 0).
// ---------------------------------------------------------------------------
__global__ void sub_kernel(float* __restrict__ out) {
    long i  = (long)blockIdx.x * blockDim.x + threadIdx.x;   // float4 index
    long n4 = (long)BATCH * VOCAB / 4;
    if (i < n4) {
        long e = i * 4;
        int  b = (int)(e / VOCAB);
        float l = g_lse[b];
        float4* o4 = (float4*)out;
        float4 v = o4[i];
        v.x -= l; v.y -= l; v.z -= l; v.w -= l;
        o4[i] = v;
    }
}

extern "C" void kernel_launch(void* const* d_in, const int* in_sizes, int n_in,
                              void* d_out, int out_size) {
    const int*   ctx = (const int*)d_in[0];     // [1024,10] int32
    const float* Wp  = (const float*)d_in[1];   // [300,50000]
    const float* Wc  = (const float*)d_in[2];   // [50000,300]
    const float* bc  = (const float*)d_in[3];   // [50000]
    const int*   pad = (const int*)d_in[4];     // scalar
    float*       out = (float*)d_out;           // [1024,50000]

    pool_kernel<<<BATCH, 320>>>(ctx, Wp, pad);
    gemm_kernel<<<dim3(8, (VOCAB + 127) / 128), 256>>>(Wc, bc, out);
    lse_kernel<<<BATCH, 256>>>(out);
    sub_kernel<<<(int)(((long)BATCH * VOCAB / 4 + 255) / 256), 256>>>(out);
}

// round 3
// speedup vs baseline: 1.1292x; 1.1292x over previous
#include <cuda_runtime.h>
#include <cuda_bf16.h>
#include <math.h>
#include <stdint.h>

#define VOCAB 50000
#define DIM   300
#define BATCH 1024
#define CTX   10
#define KP    320            // K padded: cols 0..299 = W, col 304 = bias, rest 0
#define NVT   391            // vocab tiles of 128 (391*128 = 50048)
#define NV    (NVT * 128)
#define NBT   8              // batch tiles of 128
#define NCH   5              // k-chunks of 64 cols
#define ROWB  640            // row stride bytes (320 bf16)

// ---------------- scratch (no device allocs allowed) ----------------
__device__ uint4 g_Wcb[(size_t)NV * 40];      // [NV][320] bf16 row-major (40 uint4/row)
__device__ uint4 g_poolb[BATCH * 40];         // [1024][320] bf16
__device__ float g_pmax[NVT * BATCH];
__device__ float g_psum[NVT * BATCH];
__device__ float g_lse[BATCH];

__device__ __forceinline__ uint32_t smem_u32(const void* p) {
    uint32_t a;
    asm("{ .reg .u64 t; cvta.to.shared.u64 t, %1; cvt.u32.u64 %0, t; }" : "=r"(a) : "l"(p));
    return a;
}
__device__ __forceinline__ void cp_async16(uint32_t saddr, const void* g) {
    asm volatile("cp.async.cg.shared.global [%0], [%1], 16;\n" :: "r"(saddr), "l"(g));
}
#define CP_COMMIT() asm volatile("cp.async.commit_group;\n")
#define CP_WAIT(n)  asm volatile("cp.async.wait_group %0;\n" :: "n"(n) : "memory")

#define LDSM_X4(r0, r1, r2, r3, addr) \
    asm volatile("ldmatrix.sync.aligned.m8n8.x4.shared.b16 {%0,%1,%2,%3}, [%4];" \
        : "=r"(r0), "=r"(r1), "=r"(r2), "=r"(r3) : "r"(addr))

#define MMA16816(d, a0, a1, a2, a3, b0, b1) \
    asm volatile("mma.sync.aligned.m16n8k16.row.col.f32.bf16.bf16.f32 " \
        "{%0,%1,%2,%3}, {%4,%5,%6,%7}, {%8,%9}, {%0,%1,%2,%3};\n" \
        : "+f"((d)[0]), "+f"((d)[1]), "+f"((d)[2]), "+f"((d)[3]) \
        : "r"(a0), "r"(a1), "r"(a2), "r"(a3), "r"(b0), "r"(b1))

// ---------------------------------------------------------------------------
// Kernel A: W_cls fp32 -> bf16 [NV][320], bias folded at col 304, rest zero.
// ---------------------------------------------------------------------------
__global__ void convert_kernel(const float* __restrict__ Wc, const float* __restrict__ bc) {
    int idx = blockIdx.x * blockDim.x + threadIdx.x;
    if (idx >= NV * 40) return;
    int v = idx / 40, j = idx % 40, k8 = j * 8;
    __nv_bfloat16 h[8];
    uint32_t* hu = (uint32_t*)h;
    hu[0] = hu[1] = hu[2] = hu[3] = 0u;
    if (v < VOCAB) {
        if (k8 + 8 <= DIM) {
            const float4 f0 = *(const float4*)(Wc + (size_t)v * DIM + k8);
            const float4 f1 = *(const float4*)(Wc + (size_t)v * DIM + k8 + 4);
            h[0] = __float2bfloat16(f0.x); h[1] = __float2bfloat16(f0.y);
            h[2] = __float2bfloat16(f0.z); h[3] = __float2bfloat16(f0.w);
            h[4] = __float2bfloat16(f1.x); h[5] = __float2bfloat16(f1.y);
            h[6] = __float2bfloat16(f1.z); h[7] = __float2bfloat16(f1.w);
        } else {
            #pragma unroll
            for (int jj = 0; jj < 8; ++jj) {
                int k = k8 + jj;
                float f = 0.f;
                if (k < DIM) f = Wc[(size_t)v * DIM + k];
                else if (k == DIM + 4) f = bc[v];      // bias column (k = 304)
                h[jj] = __float2bfloat16(f);
            }
        }
    }
    g_Wcb[(size_t)v * 40 + j] = *(const uint4*)h;
}

// ---------------------------------------------------------------------------
// Kernel B: masked-mean pooling -> bf16 [1024][320], col 304 = 1 (bias mult).
// ---------------------------------------------------------------------------
__global__ void pool_kernel(const int* __restrict__ ctx, const float* __restrict__ Wp,
                            const int* __restrict__ pad_idx) {
    int b = blockIdx.x;
    __shared__ int ids[CTX];
    __shared__ int pad;
    __shared__ __align__(16) __nv_bfloat16 sv[KP];
    if (threadIdx.x < CTX) ids[threadIdx.x] = ctx[b * CTX + threadIdx.x];
    if (threadIdx.x == 0)  pad = *pad_idx;
    __syncthreads();
    int d = threadIdx.x;   // 0..319
    float s = 0.f;
    if (d < DIM) {
        #pragma unroll
        for (int c = 0; c < CTX; ++c) {
            int id = ids[c];
            if (id != pad) s += Wp[(size_t)d * VOCAB + id];
        }
        s *= (1.0f / CTX);
    } else if (d == DIM + 4) {
        s = 1.0f;
    }
    sv[d] = __float2bfloat16(s);
    __syncthreads();
    if (d < 40) g_poolb[b * 40 + d] = ((const uint4*)sv)[d];
}

// ---------------------------------------------------------------------------
// Kernel C: HMMA GEMM. Block 128(v) x 128(b) x 320, 8 warps (2m x 4n),
// warp 64x32 = 4x4 m16n8k16 frags. 3-stage cp.async pipeline, 64-col chunks,
// XOR-swizzled smem + ldmatrix.x4. Epilogue: +bias (folded), stores, fused
// logsumexp partials per (vtile, batch).
// ---------------------------------------------------------------------------
#define STG_BYTES 32768u                       // per stage: 16KB A + 16KB B
#define S_LSE     (3u * STG_BYTES)             // staging: 8 warps * 32 cols * float2
#define SMEM_REQ  (3 * 32768 + 8 * 32 * 8)

__device__ __forceinline__ void issue_chunk(uint32_t smbase, int s, int c,
                                            int vbase, int bbase, int tid) {
    const char* gA = (const char*)g_Wcb  + (size_t)vbase * ROWB + c * 128;
    const char* gB = (const char*)g_poolb + (size_t)bbase * ROWB + c * 128;
    uint32_t sA = smbase + (uint32_t)s * STG_BYTES;
    uint32_t sB = sA + 16384u;
    #pragma unroll
    for (int it = 0; it < 4; ++it) {
        int idx = tid + it * 256;              // 0..1023
        int row = idx >> 3, ju = idx & 7;
        uint32_t soff = (uint32_t)((row * 8 + (ju ^ (row & 7))) * 16);
        cp_async16(sA + soff, gA + (size_t)row * ROWB + ju * 16);
        cp_async16(sB + soff, gB + (size_t)row * ROWB + ju * 16);
    }
    CP_COMMIT();
}

__global__ void __launch_bounds__(256, 2)
gemm_kernel(float* __restrict__ out) {
    extern __shared__ char smc[];
    const uint32_t smbase = smem_u32(smc);

    const int tid = threadIdx.x, wid = tid >> 5, lane = tid & 31;
    const int wm = wid >> 2, wn = wid & 3;
    const int g = lane >> 2, t = lane & 3;
    const int vt = blockIdx.y, bt = blockIdx.x;
    const int vbase = vt * 128, bbase = bt * 128;

    float acc[4][4][4];
    #pragma unroll
    for (int mi = 0; mi < 4; ++mi)
        #pragma unroll
        for (int ni = 0; ni < 4; ++ni)
            { acc[mi][ni][0] = acc[mi][ni][1] = acc[mi][ni][2] = acc[mi][ni][3] = 0.f; }

    issue_chunk(smbase, 0, 0, vbase, bbase, tid);
    issue_chunk(smbase, 1, 1, vbase, bbase, tid);

    const int r16 = lane & 15, uhi = lane >> 4;

    for (int c = 0; c < NCH; ++c) {
        if (c < NCH - 1) CP_WAIT(1); else CP_WAIT(0);
        __syncthreads();
        if (c + 2 < NCH) issue_chunk(smbase, (c + 2) % 3, c + 2, vbase, bbase, tid);

        uint32_t sA = smbase + (uint32_t)(c % 3) * STG_BYTES;
        uint32_t sB = sA + 16384u;

        #pragma unroll
        for (int ks = 0; ks < 4; ++ks) {
            const int uu = 2 * ks + uhi;
            uint32_t a[4][4], b[4][2];
            #pragma unroll
            for (int mi = 0; mi < 4; ++mi) {
                int row = wm * 64 + mi * 16 + r16;
                uint32_t ad = sA + (uint32_t)((row * 8 + (uu ^ (row & 7))) * 16);
                LDSM_X4(a[mi][0], a[mi][1], a[mi][2], a[mi][3], ad);
            }
            #pragma unroll
            for (int nj = 0; nj < 2; ++nj) {
                int row = wn * 32 + nj * 16 + r16;
                uint32_t ad = sB + (uint32_t)((row * 8 + (uu ^ (row & 7))) * 16);
                uint32_t r0, r1, r2, r3;
                LDSM_X4(r0, r1, r2, r3, ad);
                b[2 * nj][0] = r0; b[2 * nj + 1][0] = r1;
                b[2 * nj][1] = r2; b[2 * nj + 1][1] = r3;
            }
            #pragma unroll
            for (int mi = 0; mi < 4; ++mi)
                #pragma unroll
                for (int ni = 0; ni < 4; ++ni)
                    MMA16816(acc[mi][ni], a[mi][0], a[mi][1], a[mi][2], a[mi][3],
                             b[ni][0], b[ni][1]);
        }
    }

    // ---- epilogue: stores (bias already folded via k=304) ----
    #pragma unroll
    for (int mi = 0; mi < 4; ++mi) {
        int vg0 = vbase + wm * 64 + mi * 16 + g;
        int vg1 = vg0 + 8;
        #pragma unroll
        for (int ni = 0; ni < 4; ++ni) {
            int bg = bbase + wn * 32 + ni * 8 + 2 * t;
            if (vg0 < VOCAB) {
                out[(size_t)bg * VOCAB + vg0]       = acc[mi][ni][0];
                out[(size_t)(bg + 1) * VOCAB + vg0] = acc[mi][ni][1];
            }
            if (vg1 < VOCAB) {
                out[(size_t)bg * VOCAB + vg1]       = acc[mi][ni][2];
                out[(size_t)(bg + 1) * VOCAB + vg1] = acc[mi][ni][3];
            }
        }
    }

    // ---- fused logsumexp partials over this block's 128 v rows ----
    float cmax[4][2], csum[4][2];
    #pragma unroll
    for (int ni = 0; ni < 4; ++ni) { cmax[ni][0] = cmax[ni][1] = -INFINITY; }
    #pragma unroll
    for (int mi = 0; mi < 4; ++mi) {
        int vg0 = vbase + wm * 64 + mi * 16 + g;
        bool ok0 = vg0 < VOCAB, ok1 = (vg0 + 8) < VOCAB;
        #pragma unroll
        for (int ni = 0; ni < 4; ++ni) {
            if (ok0) { cmax[ni][0] = fmaxf(cmax[ni][0], acc[mi][ni][0]);
                       cmax[ni][1] = fmaxf(cmax[ni][1], acc[mi][ni][1]); }
            if (ok1) { cmax[ni][0] = fmaxf(cmax[ni][0], acc[mi][ni][2]);
                       cmax[ni][1] = fmaxf(cmax[ni][1], acc[mi][ni][3]); }
        }
    }
    #pragma unroll
    for (int ni = 0; ni < 4; ++ni)
        #pragma unroll
        for (int p = 0; p < 2; ++p) {
            cmax[ni][p] = fmaxf(cmax[ni][p], __shfl_xor_sync(0xffffffffu, cmax[ni][p], 4));
            cmax[ni][p] = fmaxf(cmax[ni][p], __shfl_xor_sync(0xffffffffu, cmax[ni][p], 8));
            cmax[ni][p] = fmaxf(cmax[ni][p], __shfl_xor_sync(0xffffffffu, cmax[ni][p], 16));
            csum[ni][p] = 0.f;
        }
    #pragma unroll
    for (int mi = 0; mi < 4; ++mi) {
        int vg0 = vbase + wm * 64 + mi * 16 + g;
        bool ok0 = vg0 < VOCAB, ok1 = (vg0 + 8) < VOCAB;
        #pragma unroll
        for (int ni = 0; ni < 4; ++ni) {
            if (ok0) { csum[ni][0] += __expf(acc[mi][ni][0] - cmax[ni][0]);
                       csum[ni][1] += __expf(acc[mi][ni][1] - cmax[ni][1]); }
            if (ok1) { csum[ni][0] += __expf(acc[mi][ni][2] - cmax[ni][0]);
                       csum[ni][1] += __expf(acc[mi][ni][3] - cmax[ni][1]); }
        }
    }
    #pragma unroll
    for (int ni = 0; ni < 4; ++ni)
        #pragma unroll
        for (int p = 0; p < 2; ++p) {
            csum[ni][p] += __shfl_xor_sync(0xffffffffu, csum[ni][p], 4);
            csum[ni][p] += __shfl_xor_sync(0xffffffffu, csum[ni][p], 8);
            csum[ni][p] += __shfl_xor_sync(0xffffffffu, csum[ni][p], 16);
        }

    float2* stg = (float2*)(smc + S_LSE);      // [8 warps][32 cols]
    __syncthreads();                            // pipeline smem dead; reuse barrier
    if (lane < 4) {
        #pragma unroll
        for (int ni = 0; ni < 4; ++ni)
            #pragma unroll
            for (int p = 0; p < 2; ++p)
                stg[wid * 32 + ni * 8 + 2 * lane + p] = make_float2(cmax[ni][p], csum[ni][p]);
    }
    __syncthreads();
    if (tid < 128) {
        int wn_ = tid >> 5, cw = tid & 31;
        float2 x = stg[wn_ * 32 + cw];            // wm = 0 warp
        float2 y = stg[(4 + wn_) * 32 + cw];      // wm = 1 warp
        float m = fmaxf(x.x, y.x);
        float s = 0.f;
        if (x.x > -INFINITY) s += x.y * __expf(x.x - m);
        if (y.x > -INFINITY) s += y.y * __expf(y.x - m);
        g_pmax[(size_t)vt * BATCH + bbase + tid] = m;
        g_psum[(size_t)vt * BATCH + bbase + tid] = s;
    }
}

// ---------------------------------------------------------------------------
// Kernel D: reduce 391 partials per batch row -> lse.
// ---------------------------------------------------------------------------
__global__ void lse_reduce() {
    int b = blockIdx.x * blockDim.x + threadIdx.x;
    if (b >= BATCH) return;
    float m = -INFINITY;
    for (int v = 0; v < NVT; ++v) m = fmaxf(m, g_pmax[(size_t)v * BATCH + b]);
    float s = 0.f;
    for (int v = 0; v < NVT; ++v) {
        float pm = g_pmax[(size_t)v * BATCH + b];
        if (pm > -INFINITY) s += g_psum[(size_t)v * BATCH + b] * __expf(pm - m);
    }
    g_lse[b] = m + logf(s);
}

// ---------------------------------------------------------------------------
// Kernel E: out[b,v] -= lse[b]  (float4, DRAM-bound)
// ---------------------------------------------------------------------------
__global__ void sub_kernel(float* __restrict__ out) {
    long i = (long)blockIdx.x * blockDim.x + threadIdx.x;
    long n4 = (long)BATCH * VOCAB / 4;
    if (i < n4) {
        long e = i * 4;
        int  b = (int)(e / VOCAB);
        float l = g_lse[b];
        float4* o4 = (float4*)out;
        float4 v = o4[i];
        v.x -= l; v.y -= l; v.z -= l; v.w -= l;
        o4[i] = v;
    }
}

extern "C" void kernel_launch(void* const* d_in, const int* in_sizes, int n_in,
                              void* d_out, int out_size) {
    const int*   ctx = (const int*)d_in[0];
    const float* Wp  = (const float*)d_in[1];
    const float* Wc  = (const float*)d_in[2];
    const float* bc  = (const float*)d_in[3];
    const int*   pad = (const int*)d_in[4];
    float*       out = (float*)d_out;

    cudaFuncSetAttribute(gemm_kernel, cudaFuncAttributeMaxDynamicSharedMemorySize, SMEM_REQ);

    convert_kernel<<<(NV * 40 + 255) / 256, 256>>>(Wc, bc);
    pool_kernel<<<BATCH, KP>>>(ctx, Wp, pad);
    gemm_kernel<<<dim3(NBT, NVT), 256, SMEM_REQ>>>(out);
    lse_reduce<<<(BATCH + 255) / 256, 256>>>();
    sub_kernel<<<(int)(((long)BATCH * VOCAB / 4 + 255) / 256), 256>>>(out);
}

// round 4
// speedup vs baseline: 1.6920x; 1.4984x over previous
#include <cuda_runtime.h>
#include <cuda_bf16.h>
#include <math.h>
#include <stdint.h>

#define VOCAB 50000
#define DIM   300
#define BATCH 1024
#define CTX   10
#define KP    320            // K padded: cols 0..299 = W, col 304 = bias, rest 0
#define NVT   391            // vocab tiles of 128 (391*128 = 50048)
#define NV    (NVT * 128)
#define NBT   8              // batch tiles of 128
#define NCH   5              // k-chunks of 64 cols
#define ROWB  640            // row stride bytes (320 bf16)
#define VSTR  50048          // scratch row stride (padded vocab)

// ---------------- scratch (no device allocs allowed) ----------------
__device__ uint4 g_Wcb[(size_t)NV * 40];            // [NV][320] bf16 row-major
__device__ uint4 g_poolb[BATCH * 40];               // [1024][320] bf16
__device__ __nv_bfloat16 g_logit[(size_t)BATCH * VSTR];  // bf16 logits scratch (~100MB)
__device__ float g_pmax[BATCH * NVT];               // [b][vt]
__device__ float g_psum[BATCH * NVT];
__device__ float g_lse[BATCH];

__device__ __forceinline__ uint32_t smem_u32(const void* p) {
    uint32_t a;
    asm("{ .reg .u64 t; cvta.to.shared.u64 t, %1; cvt.u32.u64 %0, t; }" : "=r"(a) : "l"(p));
    return a;
}
__device__ __forceinline__ void cp_async16(uint32_t saddr, const void* g) {
    asm volatile("cp.async.cg.shared.global [%0], [%1], 16;\n" :: "r"(saddr), "l"(g));
}
#define CP_COMMIT() asm volatile("cp.async.commit_group;\n")
#define CP_WAIT(n)  asm volatile("cp.async.wait_group %0;\n" :: "n"(n) : "memory")

#define LDSM_X4(r0, r1, r2, r3, addr) \
    asm volatile("ldmatrix.sync.aligned.m8n8.x4.shared.b16 {%0,%1,%2,%3}, [%4];" \
        : "=r"(r0), "=r"(r1), "=r"(r2), "=r"(r3) : "r"(addr))

#define MMA16816(d, a0, a1, a2, a3, b0, b1) \
    asm volatile("mma.sync.aligned.m16n8k16.row.col.f32.bf16.bf16.f32 " \
        "{%0,%1,%2,%3}, {%4,%5,%6,%7}, {%8,%9}, {%0,%1,%2,%3};\n" \
        : "+f"((d)[0]), "+f"((d)[1]), "+f"((d)[2]), "+f"((d)[3]) \
        : "r"(a0), "r"(a1), "r"(a2), "r"(a3), "r"(b0), "r"(b1))

// ---------------------------------------------------------------------------
// Kernel A: W_cls fp32 -> bf16 [NV][320], bias folded at col 304, rest zero.
// ---------------------------------------------------------------------------
__global__ void convert_kernel(const float* __restrict__ Wc, const float* __restrict__ bc) {
    int idx = blockIdx.x * blockDim.x + threadIdx.x;
    if (idx >= NV * 40) return;
    int v = idx / 40, j = idx % 40, k8 = j * 8;
    __nv_bfloat16 h[8];
    uint32_t* hu = (uint32_t*)h;
    hu[0] = hu[1] = hu[2] = hu[3] = 0u;
    if (v < VOCAB) {
        if (k8 + 8 <= DIM) {
            const float4 f0 = *(const float4*)(Wc + (size_t)v * DIM + k8);
            const float4 f1 = *(const float4*)(Wc + (size_t)v * DIM + k8 + 4);
            h[0] = __float2bfloat16(f0.x); h[1] = __float2bfloat16(f0.y);
            h[2] = __float2bfloat16(f0.z); h[3] = __float2bfloat16(f0.w);
            h[4] = __float2bfloat16(f1.x); h[5] = __float2bfloat16(f1.y);
            h[6] = __float2bfloat16(f1.z); h[7] = __float2bfloat16(f1.w);
        } else {
            #pragma unroll
            for (int jj = 0; jj < 8; ++jj) {
                int k = k8 + jj;
                float f = 0.f;
                if (k < DIM) f = Wc[(size_t)v * DIM + k];
                else if (k == DIM + 4) f = bc[v];      // bias column (k = 304)
                h[jj] = __float2bfloat16(f);
            }
        }
    }
    g_Wcb[(size_t)v * 40 + j] = *(const uint4*)h;
}

// ---------------------------------------------------------------------------
// Kernel B: masked-mean pooling -> bf16 [1024][320], col 304 = 1 (bias mult).
// ---------------------------------------------------------------------------
__global__ void pool_kernel(const int* __restrict__ ctx, const float* __restrict__ Wp,
                            const int* __restrict__ pad_idx) {
    int b = blockIdx.x;
    __shared__ int ids[CTX];
    __shared__ int pad;
    __shared__ __align__(16) __nv_bfloat16 sv[KP];
    if (threadIdx.x < CTX) ids[threadIdx.x] = ctx[b * CTX + threadIdx.x];
    if (threadIdx.x == 0)  pad = *pad_idx;
    __syncthreads();
    int d = threadIdx.x;   // 0..319
    float s = 0.f;
    if (d < DIM) {
        #pragma unroll
        for (int c = 0; c < CTX; ++c) {
            int id = ids[c];
            if (id != pad) s += Wp[(size_t)d * VOCAB + id];
        }
        s *= (1.0f / CTX);
    } else if (d == DIM + 4) {
        s = 1.0f;
    }
    sv[d] = __float2bfloat16(s);
    __syncthreads();
    if (d < 40) g_poolb[b * 40 + d] = ((const uint4*)sv)[d];
}

// ---------------------------------------------------------------------------
// Kernel C: HMMA GEMM 128(v) x 128(b) x 320, 8 warps (2m x 4n), 3-stage
// cp.async pipeline, swizzled smem + ldmatrix.x4. Epilogue: bf16 logit
// stores to scratch + fused logsumexp partials per (b, vtile).
// ---------------------------------------------------------------------------
#define STG_BYTES 32768u
#define S_LSE     (3u * STG_BYTES)
#define SMEM_REQ  (3 * 32768 + 8 * 32 * 8)

__device__ __forceinline__ void issue_chunk(uint32_t smbase, int s, int c,
                                            int vbase, int bbase, int tid) {
    const char* gA = (const char*)g_Wcb  + (size_t)vbase * ROWB + c * 128;
    const char* gB = (const char*)g_poolb + (size_t)bbase * ROWB + c * 128;
    uint32_t sA = smbase + (uint32_t)s * STG_BYTES;
    uint32_t sB = sA + 16384u;
    #pragma unroll
    for (int it = 0; it < 4; ++it) {
        int idx = tid + it * 256;
        int row = idx >> 3, ju = idx & 7;
        uint32_t soff = (uint32_t)((row * 8 + (ju ^ (row & 7))) * 16);
        cp_async16(sA + soff, gA + (size_t)row * ROWB + ju * 16);
        cp_async16(sB + soff, gB + (size_t)row * ROWB + ju * 16);
    }
    CP_COMMIT();
}

__global__ void __launch_bounds__(256, 2)
gemm_kernel() {
    extern __shared__ char smc[];
    const uint32_t smbase = smem_u32(smc);

    const int tid = threadIdx.x, wid = tid >> 5, lane = tid & 31;
    const int wm = wid >> 2, wn = wid & 3;
    const int g = lane >> 2, t = lane & 3;
    const int vt = blockIdx.y, bt = blockIdx.x;
    const int vbase = vt * 128, bbase = bt * 128;

    float acc[4][4][4];
    #pragma unroll
    for (int mi = 0; mi < 4; ++mi)
        #pragma unroll
        for (int ni = 0; ni < 4; ++ni)
            { acc[mi][ni][0] = acc[mi][ni][1] = acc[mi][ni][2] = acc[mi][ni][3] = 0.f; }

    issue_chunk(smbase, 0, 0, vbase, bbase, tid);
    issue_chunk(smbase, 1, 1, vbase, bbase, tid);

    const int r16 = lane & 15, uhi = lane >> 4;

    for (int c = 0; c < NCH; ++c) {
        if (c < NCH - 1) CP_WAIT(1); else CP_WAIT(0);
        __syncthreads();
        if (c + 2 < NCH) issue_chunk(smbase, (c + 2) % 3, c + 2, vbase, bbase, tid);

        uint32_t sA = smbase + (uint32_t)(c % 3) * STG_BYTES;
        uint32_t sB = sA + 16384u;

        #pragma unroll
        for (int ks = 0; ks < 4; ++ks) {
            const int uu = 2 * ks + uhi;
            uint32_t a[4][4], b[4][2];
            #pragma unroll
            for (int mi = 0; mi < 4; ++mi) {
                int row = wm * 64 + mi * 16 + r16;
                uint32_t ad = sA + (uint32_t)((row * 8 + (uu ^ (row & 7))) * 16);
                LDSM_X4(a[mi][0], a[mi][1], a[mi][2], a[mi][3], ad);
            }
            #pragma unroll
            for (int nj = 0; nj < 2; ++nj) {
                int row = wn * 32 + nj * 16 + r16;
                uint32_t ad = sB + (uint32_t)((row * 8 + (uu ^ (row & 7))) * 16);
                uint32_t r0, r1, r2, r3;
                LDSM_X4(r0, r1, r2, r3, ad);
                b[2 * nj][0] = r0; b[2 * nj + 1][0] = r1;
                b[2 * nj][1] = r2; b[2 * nj + 1][1] = r3;
            }
            #pragma unroll
            for (int mi = 0; mi < 4; ++mi)
                #pragma unroll
                for (int ni = 0; ni < 4; ++ni)
                    MMA16816(acc[mi][ni], a[mi][0], a[mi][1], a[mi][2], a[mi][3],
                             b[ni][0], b[ni][1]);
        }
    }

    // ---- epilogue: bf16 logit stores to padded scratch (always in-bounds) ----
    #pragma unroll
    for (int mi = 0; mi < 4; ++mi) {
        int vg0 = vbase + wm * 64 + mi * 16 + g;
        int vg1 = vg0 + 8;
        #pragma unroll
        for (int ni = 0; ni < 4; ++ni) {
            int bg = bbase + wn * 32 + ni * 8 + 2 * t;
            g_logit[(size_t)bg * VSTR + vg0]       = __float2bfloat16(acc[mi][ni][0]);
            g_logit[(size_t)(bg + 1) * VSTR + vg0] = __float2bfloat16(acc[mi][ni][1]);
            g_logit[(size_t)bg * VSTR + vg1]       = __float2bfloat16(acc[mi][ni][2]);
            g_logit[(size_t)(bg + 1) * VSTR + vg1] = __float2bfloat16(acc[mi][ni][3]);
        }
    }

    // ---- fused logsumexp partials over this block's 128 v rows ----
    float cmax[4][2], csum[4][2];
    #pragma unroll
    for (int ni = 0; ni < 4; ++ni) { cmax[ni][0] = cmax[ni][1] = -INFINITY; }
    #pragma unroll
    for (int mi = 0; mi < 4; ++mi) {
        int vg0 = vbase + wm * 64 + mi * 16 + g;
        bool ok0 = vg0 < VOCAB, ok1 = (vg0 + 8) < VOCAB;
        #pragma unroll
        for (int ni = 0; ni < 4; ++ni) {
            if (ok0) { cmax[ni][0] = fmaxf(cmax[ni][0], acc[mi][ni][0]);
                       cmax[ni][1] = fmaxf(cmax[ni][1], acc[mi][ni][1]); }
            if (ok1) { cmax[ni][0] = fmaxf(cmax[ni][0], acc[mi][ni][2]);
                       cmax[ni][1] = fmaxf(cmax[ni][1], acc[mi][ni][3]); }
        }
    }
    #pragma unroll
    for (int ni = 0; ni < 4; ++ni)
        #pragma unroll
        for (int p = 0; p < 2; ++p) {
            cmax[ni][p] = fmaxf(cmax[ni][p], __shfl_xor_sync(0xffffffffu, cmax[ni][p], 4));
            cmax[ni][p] = fmaxf(cmax[ni][p], __shfl_xor_sync(0xffffffffu, cmax[ni][p], 8));
            cmax[ni][p] = fmaxf(cmax[ni][p], __shfl_xor_sync(0xffffffffu, cmax[ni][p], 16));
            csum[ni][p] = 0.f;
        }
    #pragma unroll
    for (int mi = 0; mi < 4; ++mi) {
        int vg0 = vbase + wm * 64 + mi * 16 + g;
        bool ok0 = vg0 < VOCAB, ok1 = (vg0 + 8) < VOCAB;
        #pragma unroll
        for (int ni = 0; ni < 4; ++ni) {
            if (ok0) { csum[ni][0] += __expf(acc[mi][ni][0] - cmax[ni][0]);
                       csum[ni][1] += __expf(acc[mi][ni][1] - cmax[ni][1]); }
            if (ok1) { csum[ni][0] += __expf(acc[mi][ni][2] - cmax[ni][0]);
                       csum[ni][1] += __expf(acc[mi][ni][3] - cmax[ni][1]); }
        }
    }
    #pragma unroll
    for (int ni = 0; ni < 4; ++ni)
        #pragma unroll
        for (int p = 0; p < 2; ++p) {
            csum[ni][p] += __shfl_xor_sync(0xffffffffu, csum[ni][p], 4);
            csum[ni][p] += __shfl_xor_sync(0xffffffffu, csum[ni][p], 8);
            csum[ni][p] += __shfl_xor_sync(0xffffffffu, csum[ni][p], 16);
        }

    float2* stg = (float2*)(smc + S_LSE);
    __syncthreads();
    if (lane < 4) {
        #pragma unroll
        for (int ni = 0; ni < 4; ++ni)
            #pragma unroll
            for (int p = 0; p < 2; ++p)
                stg[wid * 32 + ni * 8 + 2 * lane + p] = make_float2(cmax[ni][p], csum[ni][p]);
    }
    __syncthreads();
    if (tid < 128) {
        int wn_ = tid >> 5, cw = tid & 31;
        float2 x = stg[wn_ * 32 + cw];
        float2 y = stg[(4 + wn_) * 32 + cw];
        float m = fmaxf(x.x, y.x);
        float s = 0.f;
        if (x.x > -INFINITY) s += x.y * __expf(x.x - m);
        if (y.x > -INFINITY) s += y.y * __expf(y.x - m);
        g_pmax[(size_t)(bbase + tid) * NVT + vt] = m;   // [b][vt] contiguous per row
        g_psum[(size_t)(bbase + tid) * NVT + vt] = s;
    }
}

// ---------------------------------------------------------------------------
// Kernel D: parallel lse reduce — one block per batch row.
// ---------------------------------------------------------------------------
__global__ void lse_kernel() {
    int b = blockIdx.x;
    int t = threadIdx.x;                       // 128 threads
    const float* pm = g_pmax + (size_t)b * NVT;
    const float* ps = g_psum + (size_t)b * NVT;
    float m = -INFINITY, s = 0.f;
    for (int v = t; v < NVT; v += 128) {
        float xm = pm[v], xs = ps[v];
        float nm = fmaxf(m, xm);
        s = s * __expf(m - nm) + xs * __expf(xm - nm);
        m = nm;
    }
    #pragma unroll
    for (int off = 16; off > 0; off >>= 1) {
        float om = __shfl_xor_sync(0xffffffffu, m, off);
        float os = __shfl_xor_sync(0xffffffffu, s, off);
        float nm = fmaxf(m, om);
        s = s * __expf(m - nm) + os * __expf(om - nm);
        m = nm;
    }
    __shared__ float sm[4], ss[4];
    if ((t & 31) == 0) { sm[t >> 5] = m; ss[t >> 5] = s; }
    __syncthreads();
    if (t == 0) {
        float M = fmaxf(fmaxf(sm[0], sm[1]), fmaxf(sm[2], sm[3]));
        float S = ss[0] * __expf(sm[0] - M) + ss[1] * __expf(sm[1] - M)
                + ss[2] * __expf(sm[2] - M) + ss[3] * __expf(sm[3] - M);
        g_lse[b] = M + logf(S);
    }
}

// ---------------------------------------------------------------------------
// Kernel E: out[b,v] = bf16_logit[b,v] - lse[b]   (read 8 bf16, write 2 float4)
// ---------------------------------------------------------------------------
__global__ void sub_kernel(float* __restrict__ out) {
    long i = (long)blockIdx.x * blockDim.x + threadIdx.x;   // 8-elem group id
    const long ng = (long)BATCH * (VOCAB / 8);
    if (i >= ng) return;
    int b = (int)(i / (VOCAB / 8));
    int j = (int)(i % (VOCAB / 8)) * 8;
    float l = g_lse[b];
    const uint4 pkt = *(const uint4*)(g_logit + (size_t)b * VSTR + j);
    const __nv_bfloat16* h = (const __nv_bfloat16*)&pkt;
    float4 o0, o1;
    o0.x = __bfloat162float(h[0]) - l; o0.y = __bfloat162float(h[1]) - l;
    o0.z = __bfloat162float(h[2]) - l; o0.w = __bfloat162float(h[3]) - l;
    o1.x = __bfloat162float(h[4]) - l; o1.y = __bfloat162float(h[5]) - l;
    o1.z = __bfloat162float(h[6]) - l; o1.w = __bfloat162float(h[7]) - l;
    float4* op = (float4*)(out + (size_t)b * VOCAB + j);
    op[0] = o0; op[1] = o1;
}

extern "C" void kernel_launch(void* const* d_in, const int* in_sizes, int n_in,
                              void* d_out, int out_size) {
    const int*   ctx = (const int*)d_in[0];
    const float* Wp  = (const float*)d_in[1];
    const float* Wc  = (const float*)d_in[2];
    const float* bc  = (const float*)d_in[3];
    const int*   pad = (const int*)d_in[4];
    float*       out = (float*)d_out;

    cudaFuncSetAttribute(gemm_kernel, cudaFuncAttributeMaxDynamicSharedMemorySize, SMEM_REQ);

    convert_kernel<<<(NV * 40 + 255) / 256, 256>>>(Wc, bc);
    pool_kernel<<<BATCH, KP>>>(ctx, Wp, pad);
    gemm_kernel<<<dim3(NBT, NVT), 256, SMEM_REQ>>>();
    lse_kernel<<<BATCH, 128>>>();
    sub_kernel<<<(int)(((long)BATCH * (VOCAB / 8) + 255) / 256), 256>>>(out);
}